// round 3
// baseline (speedup 1.0000x reference)
#include <cuda_runtime.h>
#include <cstdint>
#include <cstddef>
#include <math.h>

#define DI __device__ __forceinline__

static constexpr int NR = 8192;
static constexpr int HD = 256;
static constexpr int BM = 128;
static constexpr int BN = 128;
static constexpr int BK = 64;
static constexpr int STAGES = 3;

// SMEM: deg[128] floats, then 3 A stages, then 3 B stages
// A stage: 128 rows x 68 floats (64 data + 4 pad) = 34816 B
// B stage:  64 rows x 136 floats (128 data + 8 pad) = 34816 B
static constexpr int A_ROW_F = 68;
static constexpr int B_ROW_F = 136;
static constexpr int STAGE_F = 8704;                 // floats per stage (both)
static constexpr int SMEM_DEG_B = 512;
static constexpr int SMEM_TOTAL = SMEM_DEG_B + 2 * STAGES * STAGE_F * 4;  // 209408

__device__ float g_P[(size_t)NR * HD];               // inputs @ W

DI uint32_t smem_u32(const void* p) {
    uint32_t a;
    asm("{ .reg .u64 t; cvta.to.shared.u64 t, %1; cvt.u32.u64 %0, t; }" : "=r"(a) : "l"(p));
    return a;
}
DI void cp_async16(uint32_t dst, const void* src) {
    asm volatile("cp.async.cg.shared.global [%0], [%1], 16;" :: "r"(dst), "l"(src) : "memory");
}
DI void cp_commit() { asm volatile("cp.async.commit_group;" ::: "memory"); }
template <int N> DI void cp_wait() { asm volatile("cp.async.wait_group %0;" :: "n"(N) : "memory"); }
DI uint32_t f2tf32(float f) {
    uint32_t u;
    asm("cvt.rna.tf32.f32 %0, %1;" : "=r"(u) : "f"(f));
    return u;
}
DI void mma_tf32(float* d, const uint32_t* a, const uint32_t* b) {
    asm volatile(
        "mma.sync.aligned.m16n8k8.row.col.f32.tf32.tf32.f32 "
        "{%0,%1,%2,%3}, {%4,%5,%6,%7}, {%8,%9}, {%0,%1,%2,%3};"
        : "+f"(d[0]), "+f"(d[1]), "+f"(d[2]), "+f"(d[3])
        : "r"(a[0]), "r"(a[1]), "r"(a[2]), "r"(a[3]), "r"(b[0]), "r"(b[1]));
}

// Loader: A tile [BM][BK] from A (row-major, lda), B tile [BK][BN] from B (row-major, ldb)
DI void load_chunk(float* sA, float* sB, int s,
                   const float* __restrict__ A, int lda, int R0,
                   const float* __restrict__ B, int ldb, int N0,
                   int k0, int tid) {
    uint32_t aAddr = smem_u32(sA + s * STAGE_F);
    uint32_t bAddr = smem_u32(sB + s * STAGE_F);
#pragma unroll
    for (int i = 0; i < 8; ++i) {                        // A: 2048 x 16B
        int idx = tid + i * 256;
        int r = idx >> 4, c = idx & 15;                  // 16 x 16B per 64-float row
        cp_async16(aAddr + (uint32_t)(r * (A_ROW_F * 4) + c * 16),
                   A + (size_t)(R0 + r) * lda + k0 + c * 4);
    }
#pragma unroll
    for (int i = 0; i < 8; ++i) {                        // B: 2048 x 16B
        int idx = tid + i * 256;
        int r = idx >> 5, c = idx & 31;                  // 32 x 16B per 128-float row
        cp_async16(bAddr + (uint32_t)(r * (B_ROW_F * 4) + c * 16),
                   B + (size_t)(k0 + r) * ldb + N0 + c * 4);
    }
}

// MODE 0: g_P[i][h] = sum_k inputs[i][k] * W[k][h]          (A=inputs, Bext=W)
// MODE 1: out[r][n] = tanh((sum_k adj[r][k]*P[k][n] + P[r][n]) / (rowsum(adj[r])+1) + b[n])
template <int MODE>
__global__ void __launch_bounds__(256, 1)
gemm_gcn(const float* __restrict__ A, const float* __restrict__ Bext,
         float* __restrict__ out, const float* __restrict__ bias) {
    extern __shared__ char smem[];
    float* sdeg = (float*)smem;
    float* sA = (float*)(smem + SMEM_DEG_B);
    float* sB = sA + STAGES * STAGE_F;

    const int tid = threadIdx.x;
    const int lane = tid & 31;
    const int wid = tid >> 5;
    const int wm = wid >> 2;            // 0..1  (M dir)
    const int wn = wid & 3;             // 0..3  (N dir)
    const int q = lane >> 2;            // group id 0..7
    const int c4 = lane & 3;            // 0..3

    const int Mt = blockIdx.x >> 1;
    const int Nt = blockIdx.x & 1;
    const int R0 = Mt * BM;
    const int N0 = Nt * BN;

    const int lda = (MODE == 0) ? HD : NR;
    const float* Bp = (MODE == 0) ? Bext : g_P;
    const int ldb = HD;
    const int NCH = ((MODE == 0) ? HD : NR) / BK;

    float acc[4][4][4];
#pragma unroll
    for (int i = 0; i < 4; ++i)
#pragma unroll
        for (int j = 0; j < 4; ++j)
#pragma unroll
            for (int e = 0; e < 4; ++e) acc[i][j][e] = 0.0f;
    float dsum[4][2];
#pragma unroll
    for (int i = 0; i < 4; ++i) dsum[i][0] = dsum[i][1] = 0.0f;

    // prologue
#pragma unroll
    for (int s = 0; s < STAGES - 1; ++s) {
        load_chunk(sA, sB, s, A, lda, R0, Bp, ldb, N0, s * BK, tid);
        cp_commit();
    }

    // per-thread fragment bases (float indices)
    const int aBase = (wm * 64 + q) * A_ROW_F + c4;      // + mt*16*A_ROW_F + ks*8 (+4)
    const int bBase = c4 * B_ROW_F + (wn * 32 + q);      // + ks*8*B_ROW_F + nt*8 (+4*B_ROW_F)

    for (int kc = 0; kc < NCH; ++kc) {
        const int s = kc % STAGES;
        const int cn = kc + STAGES - 1;
        if (cn < NCH) load_chunk(sA, sB, cn % STAGES, A, lda, R0, Bp, ldb, N0, cn * BK, tid);
        cp_commit();
        cp_wait<STAGES - 1>();
        __syncthreads();

        const float* aS = sA + s * STAGE_F;
        const float* bS = sB + s * STAGE_F;
#pragma unroll
        for (int ks = 0; ks < BK / 8; ++ks) {
            uint32_t af[4][4];
#pragma unroll
            for (int mt = 0; mt < 4; ++mt) {
                int base = aBase + mt * 16 * A_ROW_F + ks * 8;
                float f0 = aS[base];
                float f1 = aS[base + 8 * A_ROW_F];
                float f2 = aS[base + 4];
                float f3 = aS[base + 8 * A_ROW_F + 4];
                if (MODE == 1 && wn == 0) {
                    dsum[mt][0] += f0 + f2;
                    dsum[mt][1] += f1 + f3;
                }
                af[mt][0] = f2tf32(f0);
                af[mt][1] = f2tf32(f1);
                af[mt][2] = f2tf32(f2);
                af[mt][3] = f2tf32(f3);
            }
            uint32_t bf[4][2];
#pragma unroll
            for (int nt = 0; nt < 4; ++nt) {
                int base = bBase + ks * 8 * B_ROW_F + nt * 8;
                bf[nt][0] = f2tf32(bS[base]);
                bf[nt][1] = f2tf32(bS[base + 4 * B_ROW_F]);
            }
#pragma unroll
            for (int mt = 0; mt < 4; ++mt)
#pragma unroll
                for (int nt = 0; nt < 4; ++nt)
                    mma_tf32(acc[mt][nt], af[mt], bf[nt]);
        }
        __syncthreads();
    }

    if (MODE == 0) {
        // write P row-major
#pragma unroll
        for (int mt = 0; mt < 4; ++mt) {
            int rlo = R0 + wm * 64 + mt * 16 + q;
#pragma unroll
            for (int nt = 0; nt < 4; ++nt) {
                int col = N0 + wn * 32 + nt * 8 + 2 * c4;
                float2 vlo = make_float2(acc[mt][nt][0], acc[mt][nt][1]);
                float2 vhi = make_float2(acc[mt][nt][2], acc[mt][nt][3]);
                *(float2*)&g_P[(size_t)rlo * HD + col] = vlo;
                *(float2*)&g_P[(size_t)(rlo + 8) * HD + col] = vhi;
            }
        }
    } else {
        // reduce degree partials across the quad, publish via SMEM
        if (wn == 0) {
#pragma unroll
            for (int mt = 0; mt < 4; ++mt) {
#pragma unroll
                for (int h = 0; h < 2; ++h) {
                    float v = dsum[mt][h];
                    v += __shfl_xor_sync(0xffffffffu, v, 1);
                    v += __shfl_xor_sync(0xffffffffu, v, 2);
                    dsum[mt][h] = v;
                }
                if (c4 == 0) {
                    sdeg[wm * 64 + mt * 16 + q] = dsum[mt][0];
                    sdeg[wm * 64 + mt * 16 + q + 8] = dsum[mt][1];
                }
            }
        }
        __syncthreads();
#pragma unroll
        for (int mt = 0; mt < 4; ++mt) {
            int lrow = wm * 64 + mt * 16 + q;
            int rlo = R0 + lrow;
            int rhi = rlo + 8;
            float invlo = 1.0f / (sdeg[lrow] + 1.0f);
            float invhi = 1.0f / (sdeg[lrow + 8] + 1.0f);
#pragma unroll
            for (int nt = 0; nt < 4; ++nt) {
                int col = N0 + wn * 32 + nt * 8 + 2 * c4;
                float2 plo = *(const float2*)&g_P[(size_t)rlo * HD + col];
                float2 phi = *(const float2*)&g_P[(size_t)rhi * HD + col];
                float2 bb = *(const float2*)&bias[col];
                float2 olo, ohi;
                olo.x = tanhf((acc[mt][nt][0] + plo.x) * invlo + bb.x);
                olo.y = tanhf((acc[mt][nt][1] + plo.y) * invlo + bb.y);
                ohi.x = tanhf((acc[mt][nt][2] + phi.x) * invhi + bb.x);
                ohi.y = tanhf((acc[mt][nt][3] + phi.y) * invhi + bb.y);
                *(float2*)&out[(size_t)rlo * HD + col] = olo;
                *(float2*)&out[(size_t)rhi * HD + col] = ohi;
            }
        }
    }
}

extern "C" void kernel_launch(void* const* d_in, const int* in_sizes, int n_in,
                              void* d_out, int out_size) {
    const float* inputs = (const float*)d_in[0];
    const float* adj    = (const float*)d_in[1];
    const float* W      = (const float*)d_in[2];
    const float* b      = (const float*)d_in[3];
    float* out = (float*)d_out;

    cudaFuncSetAttribute(gemm_gcn<0>, cudaFuncAttributeMaxDynamicSharedMemorySize, SMEM_TOTAL);
    cudaFuncSetAttribute(gemm_gcn<1>, cudaFuncAttributeMaxDynamicSharedMemorySize, SMEM_TOTAL);

    // GEMM1: P = inputs @ W   (grid: 64 M-tiles x 2 N-tiles)
    gemm_gcn<0><<<(NR / BM) * (HD / BN), 256, SMEM_TOTAL>>>(inputs, W, nullptr, nullptr);
    // GEMM2 + fused normalize/self-loop/bias/tanh
    gemm_gcn<1><<<(NR / BM) * (HD / BN), 256, SMEM_TOTAL>>>(adj, nullptr, out, b);
}